// round 9
// baseline (speedup 1.0000x reference)
#include <cuda_runtime.h>
#include <cstddef>

// GCN 2-layer via per-call CSR build + gather (no fp atomics in aggregation).
// N=100000, E=3.2M, DIN=128, DH=32, DOUT=2. edge_index is int32.

static constexpr int NMAX  = 100000;
static constexpr long long EMAX = 3300000;
static constexpr int D_IN  = 128;
static constexpr int D_H   = 32;
static constexpr int D_OUT = 2;
static constexpr int SCAN_BLK = 2048;      // elements per scan block (256 thr x 8)

__device__ __align__(16) float g_dinv[NMAX];
__device__ __align__(16) float g_m1s [(size_t)NMAX * D_H];   // (x@W1)*dinv[row]
__device__ __align__(16) float g_p2  [(size_t)NMAX * D_OUT]; // (relu(agg1+b1)@W2)*dinv
__device__ __align__(16) int   g_cnt[NMAX];
__device__ __align__(16) int   g_off[NMAX];                  // becomes END after k_fill
__device__ int   g_adj[EMAX];              // src indices grouped by dst
__device__ int   g_bsum[(NMAX + SCAN_BLK - 1) / SCAN_BLK];

// ---- CSR build --------------------------------------------------------------
__global__ void k_zero(int n4) {            // n4 = ceil(n/4)
    int i = blockIdx.x * blockDim.x + threadIdx.x;
    if (i < n4) ((int4*)g_cnt)[i] = make_int4(0, 0, 0, 0);
}

__global__ void k_count(const int* __restrict__ dst, int E) {
    int i = blockIdx.x * blockDim.x + threadIdx.x;
    int e = i * 4;
    if (e + 3 < E) {
        int4 d = *(const int4*)(dst + e);
        atomicAdd(&g_cnt[d.x], 1);
        atomicAdd(&g_cnt[d.y], 1);
        atomicAdd(&g_cnt[d.z], 1);
        atomicAdd(&g_cnt[d.w], 1);
    } else {
        for (; e < E; e++) atomicAdd(&g_cnt[dst[e]], 1);
    }
}

// Per-block exclusive scan over 2048 counts + dinv. Writes block sums.
__global__ void __launch_bounds__(256) k_part(int n) {
    __shared__ int sp[256];
    int base = blockIdx.x * SCAN_BLK + threadIdx.x * 8;
    int v[8]; int s = 0;
    #pragma unroll
    for (int j = 0; j < 8; j++) {
        int i = base + j;
        v[j] = (i < n) ? g_cnt[i] : 0;
        s += v[j];
    }
    sp[threadIdx.x] = s; __syncthreads();
    for (int ofs = 1; ofs < 256; ofs <<= 1) {
        int t = (threadIdx.x >= ofs) ? sp[threadIdx.x - ofs] : 0;
        __syncthreads();
        sp[threadIdx.x] += t;
        __syncthreads();
    }
    int excl = threadIdx.x ? sp[threadIdx.x - 1] : 0;
    #pragma unroll
    for (int j = 0; j < 8; j++) {
        int i = base + j;
        if (i < n) {
            g_off[i]  = excl; excl += v[j];
            g_dinv[i] = rsqrtf((float)v[j] + 1.0f);   // +1 self loop
        }
    }
    if (threadIdx.x == 255) g_bsum[blockIdx.x] = sp[255];
}

// Add cross-block prefix. Each 256-node block lies inside ONE scan block.
__global__ void k_finoff(int n) {
    int sb = (blockIdx.x * 256) / SCAN_BLK;    // uniform per CTA
    int pre = 0;
    for (int j = 0; j < sb; j++) pre += g_bsum[j];   // broadcast loads
    int i = blockIdx.x * 256 + threadIdx.x;
    if (i < n) g_off[i] += pre;
}

__global__ void k_fill(const int* __restrict__ src, const int* __restrict__ dst, int E) {
    int e = blockIdx.x * blockDim.x + threadIdx.x;
    if (e >= E) return;
    int d = dst[e];
    int pos = atomicAdd(&g_off[d], 1);         // g_off becomes END pointer
    g_adj[pos] = src[e];
}

// ---- layer 1 GEMM: m1s = (x@W1)*dinv ---------------------------------------
// 128 thr = 4 warps x 8 rows; smem 32KB -> ~7 blocks/SM.
__global__ void __launch_bounds__(128) k_gemm1(const float* __restrict__ x,
                                               const float* __restrict__ W1, int n) {
    __shared__ float  sWp[D_IN * D_H];       // 16 KB, k-pair interleaved transposed W
    __shared__ float4 sx[4][8][D_IN / 4];    // 16 KB
    int tid = threadIdx.x;
    for (int i = tid; i < D_IN * D_H; i += 128) {
        int k = i >> 5, c = i & 31;
        sWp[(k >> 1) * 64 + c * 2 + (k & 1)] = W1[i];
    }
    int warp = tid >> 5, lane = tid & 31;
    int row0 = blockIdx.x * 32 + warp * 8;
    #pragma unroll
    for (int r = 0; r < 8; r++) {
        int row = row0 + r;
        if (row < n)
            sx[warp][r][lane] = ((const float4*)(x + (size_t)row * D_IN))[lane];
    }
    __syncthreads();

    const ulonglong2* sxp = (const ulonglong2*)&sx[warp][0][0];
    const unsigned long long* sWq = (const unsigned long long*)sWp;
    unsigned long long acc[8] = {0ull,0ull,0ull,0ull,0ull,0ull,0ull,0ull};
    #pragma unroll 4
    for (int k4 = 0; k4 < D_IN / 4; k4++) {
        unsigned long long w01 = sWq[(k4 * 2 + 0) * 32 + lane];
        unsigned long long w23 = sWq[(k4 * 2 + 1) * 32 + lane];
        #pragma unroll
        for (int r = 0; r < 8; r++) {
            ulonglong2 xp = sxp[r * 32 + k4];
            asm("fma.rn.f32x2 %0, %1, %2, %0;" : "+l"(acc[r]) : "l"(xp.x), "l"(w01));
            asm("fma.rn.f32x2 %0, %1, %2, %0;" : "+l"(acc[r]) : "l"(xp.y), "l"(w23));
        }
    }
    #pragma unroll
    for (int r = 0; r < 8; r++) {
        int row = row0 + r;
        if (row < n) {
            float lo = __uint_as_float((unsigned)(acc[r] & 0xffffffffull));
            float hi = __uint_as_float((unsigned)(acc[r] >> 32));
            g_m1s[(size_t)row * D_H + lane] = (lo + hi) * g_dinv[row];
        }
    }
}

// ---- fused layer-1 gather + layer-2 transform ------------------------------
// Warp per dst node; lane = feature dim. 8 independent accumulator chains.
__global__ void __launch_bounds__(256) k_gather1(const float* __restrict__ b1,
                                                 const float* __restrict__ W2,
                                                 const float* __restrict__ b2,
                                                 float* __restrict__ out, int n) {
    int w = (int)((blockIdx.x * 256 + threadIdx.x) >> 5);
    int lane = threadIdx.x & 31;
    if (w >= n) return;
    int cnt = g_cnt[w];
    int start = g_off[w] - cnt;                 // off is END after k_fill
    float dv = g_dinv[w];

    float a[8] = {0.f,0.f,0.f,0.f,0.f,0.f,0.f,0.f};
    int j = 0;
    for (; j + 32 <= cnt; j += 32) {
        int idx = g_adj[start + j + lane];
        #pragma unroll
        for (int t = 0; t < 32; t += 8) {
            #pragma unroll
            for (int u = 0; u < 8; u++) {
                int s = __shfl_sync(0xffffffffu, idx, t + u);
                a[u] += g_m1s[(size_t)s * D_H + lane];
            }
        }
    }
    if (j < cnt) {
        int rem = cnt - j;
        int idx = (lane < rem) ? g_adj[start + j + lane] : 0;
        int t = 0;
        for (; t + 8 <= rem; t += 8) {
            #pragma unroll
            for (int u = 0; u < 8; u++) {
                int s = __shfl_sync(0xffffffffu, idx, t + u);
                a[u] += g_m1s[(size_t)s * D_H + lane];
            }
        }
        for (; t < rem; t++) {
            int s = __shfl_sync(0xffffffffu, idx, t);
            a[t & 7] += g_m1s[(size_t)s * D_H + lane];
        }
    }
    float acc = ((a[0]+a[1]) + (a[2]+a[3])) + ((a[4]+a[5]) + (a[6]+a[7]));
    acc += g_m1s[(size_t)w * D_H + lane];          // self loop (m1s = m1*dinv)
    float h = fmaxf(acc * dv + __ldg(&b1[lane]), 0.f);
    float p0 = h * __ldg(&W2[lane * 2 + 0]);
    float p1 = h * __ldg(&W2[lane * 2 + 1]);
    #pragma unroll
    for (int o = 16; o; o >>= 1) {
        p0 += __shfl_xor_sync(0xffffffffu, p0, o);
        p1 += __shfl_xor_sync(0xffffffffu, p1, o);
    }
    if (lane == 0) {
        float q0 = p0 * dv, q1 = p1 * dv;          // pre-scaled by dinv[src]
        g_p2[(size_t)w * 2 + 0] = q0;
        g_p2[(size_t)w * 2 + 1] = q1;
        out[(size_t)w * 2 + 0] = __ldg(&b2[0]) + q0 * dv;   // bias + self loop
        out[(size_t)w * 2 + 1] = __ldg(&b2[1]) + q1 * dv;
    }
}

// ---- layer-2 gather ---------------------------------------------------------
__global__ void __launch_bounds__(256) k_gather2(float* __restrict__ out, int n) {
    int w = (int)((blockIdx.x * 256 + threadIdx.x) >> 5);
    int lane = threadIdx.x & 31;
    if (w >= n) return;
    int cnt = g_cnt[w];
    int start = g_off[w] - cnt;
    float a0 = 0.f, a1 = 0.f;
    for (int j = lane; j < cnt; j += 32) {
        int s = g_adj[start + j];
        float2 p = *(const float2*)(g_p2 + (size_t)s * 2);
        a0 += p.x; a1 += p.y;
    }
    #pragma unroll
    for (int o = 16; o; o >>= 1) {
        a0 += __shfl_xor_sync(0xffffffffu, a0, o);
        a1 += __shfl_xor_sync(0xffffffffu, a1, o);
    }
    if (lane == 0) {
        float dv = g_dinv[w];
        out[(size_t)w * 2 + 0] += a0 * dv;
        out[(size_t)w * 2 + 1] += a1 * dv;
    }
}

extern "C" void kernel_launch(void* const* d_in, const int* in_sizes, int n_in,
                              void* d_out, int out_size) {
    const float* x   = (const float*)d_in[0];
    const int*   ei  = (const int*)d_in[1];
    const float* W1  = (const float*)d_in[2];
    const float* b1  = (const float*)d_in[3];
    const float* W2  = (const float*)d_in[4];
    const float* b2  = (const float*)d_in[5];
    float*       out = (float*)d_out;

    int n = in_sizes[0] / D_IN;
    int E = in_sizes[1] / 2;
    const int* src = ei;
    const int* dst = ei + E;
    int nb = (n + SCAN_BLK - 1) / SCAN_BLK;
    int n4 = (n + 3) / 4;
    int e4 = (E + 3) / 4;

    k_zero   <<<(n4 + 255) / 256, 256>>>(n4);
    k_count  <<<(e4 + 255) / 256, 256>>>(dst, E);
    k_part   <<<nb, 256>>>(n);
    k_finoff <<<(n + 255) / 256, 256>>>(n);
    k_fill   <<<(E + 255) / 256, 256>>>(src, dst, E);
    k_gemm1  <<<(n + 31) / 32, 128>>>(x, W1, n);
    k_gather1<<<(n * 32 + 255) / 256, 256>>>(b1, W2, b2, out, n);
    k_gather2<<<(n * 32 + 255) / 256, 256>>>(out, n);
}